// round 16
// baseline (speedup 1.0000x reference)
#include <cuda_runtime.h>
#include <math_constants.h>

#define B_ROWS 8192
#define VOCAB  32000
#define KNEG   5
#define SDOM   100
#define EPSV   1e-10f
#define TPB    256

// Self-resetting accumulator state for graph-replay determinism.
__device__ double       g_acc   = 0.0;
__device__ unsigned int g_count = 0;

__global__ __launch_bounds__(TPB, 8)   // 8 CTAs/SM (<=32 regs)
void bo4_fused_kernel(const float* __restrict__ yHat,
                      const float* __restrict__ prob,
                      const int*   __restrict__ y,
                      const int*   __restrict__ ind,
                      float*       __restrict__ out)
{
    const int b    = blockIdx.x;
    const int tid  = threadIdx.x;
    const int wid  = tid >> 5;
    const int lane = tid & 31;

    const float*  row  = yHat + (size_t)b * VOCAB;
    const float4* row4 = reinterpret_cast<const float4*>(row);

    // ---- PREFETCH tail operands (warp 0): their DRAM/L2 latency ----
    // ---- overlaps the row scan instead of trailing it.           ----
    float pre_yg = 0.f, pre_c = 0.f, pre_p = 1.f;
    if (wid == 0) {
        const int yy = __ldg(y + b);            // uniform across warp
        pre_yg = __ldg(row + yy);
        if (lane < KNEG) {
            const int idx = __ldg(ind + b * KNEG + lane);   // idx in [0,100)
            pre_c = __ldg(row + idx);
            pre_p = __ldg(prob + (size_t)yy * SDOM + idx);
        }
    }

    // ---- row max over 8000 float4: 4 loads front-batched per iter ----
    // ---- (MLP_p1=4), two independent FMAX accumulator chains.     ----
    float m0 = -CUDART_INF_F, m1 = -CUDART_INF_F;
    int i = tid;
    for (; i + 3 * TPB < VOCAB / 4; i += 4 * TPB) {
        float4 a = __ldcs(row4 + i);
        float4 c = __ldcs(row4 + i +     TPB);
        float4 e = __ldcs(row4 + i + 2 * TPB);
        float4 g = __ldcs(row4 + i + 3 * TPB);
        m0 = fmaxf(m0, fmaxf(fmaxf(a.x, a.y), fmaxf(a.z, a.w)));
        m1 = fmaxf(m1, fmaxf(fmaxf(c.x, c.y), fmaxf(c.z, c.w)));
        m0 = fmaxf(m0, fmaxf(fmaxf(e.x, e.y), fmaxf(e.z, e.w)));
        m1 = fmaxf(m1, fmaxf(fmaxf(g.x, g.y), fmaxf(g.z, g.w)));
    }
    for (; i < VOCAB / 4; i += TPB) {               // cleanup (<=3 strides)
        float4 a = __ldcs(row4 + i);
        m0 = fmaxf(m0, fmaxf(fmaxf(a.x, a.y), fmaxf(a.z, a.w)));
    }
    float m = fmaxf(m0, m1);
    #pragma unroll
    for (int o = 16; o > 0; o >>= 1)
        m = fmaxf(m, __shfl_xor_sync(0xFFFFFFFFu, m, o));

    __shared__ float smax[8];
    if (lane == 0) smax[wid] = m;
    __syncthreads();

    // ---- warp-cooperative tail: pure ALU, operands already in regs ----
    if (wid == 0) {
        float mm = smax[0];
        #pragma unroll
        for (int w = 1; w < 8; w++) mm = fmaxf(mm, smax[w]);

        const float pinv = 1.0f / pre_p;                        // lanes>=K: 1.0
        float qv = (lane < KNEG) ? pinv : CUDART_INF_F;
        #pragma unroll
        for (int o = 16; o > 0; o >>= 1)
            qv = fminf(qv, __shfl_xor_sync(0xFFFFFFFFu, qv, o));

        const float ck = (lane < KNEG) ? pinv * __expf(pre_c - mm) : 0.f;
        float sc = ck;
        #pragma unroll
        for (int o = 16; o > 0; o >>= 1)
            sc += __shfl_xor_sync(0xFFFFFFFFu, sc, o);

        const float Yg  = qv * __expf(pre_yg - mm);   // pre_yg lane-uniform
        const float inv = 1.0f / (Yg + sc);

        float lt = (lane < KNEG) ? __logf(1.0f - ck * inv + EPSV) : 0.f;
        #pragma unroll
        for (int o = 16; o > 0; o >>= 1)
            lt += __shfl_xor_sync(0xFFFFFFFFu, lt, o);

        if (lane == 0) {
            const float term = __logf(Yg * inv + EPSV) + lt;
            atomicAdd(&g_acc, (double)term);
            __threadfence();
            unsigned int t = atomicAdd(&g_count, 1u);
            if (t == (unsigned)(B_ROWS - 1)) {
                out[0] = (float)(-g_acc / (double)(B_ROWS * (KNEG + 1)));
                g_acc   = 0.0;      // restore state for next graph replay
                g_count = 0u;
                __threadfence();
            }
        }
    }
}

extern "C" void kernel_launch(void* const* d_in, const int* in_sizes, int n_in,
                              void* d_out, int out_size)
{
    const float* yHat = (const float*)d_in[0];   // [B, V] fp32
    const float* prob = (const float*)d_in[1];   // [V, S] fp32
    const int*   y    = (const int*)  d_in[2];   // [B]    int32
    const int*   ind  = (const int*)  d_in[3];   // [B, K] int32

    bo4_fused_kernel<<<B_ROWS, TPB>>>(yHat, prob, y, ind, (float*)d_out);
}

// round 17
// speedup vs baseline: 1.0154x; 1.0154x over previous
#include <cuda_runtime.h>
#include <math_constants.h>

#define B_ROWS 8192
#define VOCAB  32000
#define KNEG   5
#define SDOM   100
#define EPSV   1e-10f

// Self-resetting accumulator state for graph-replay determinism.
__device__ double       g_acc   = 0.0;
__device__ unsigned int g_count = 0;

__global__ __launch_bounds__(256, 8)   // force 8 CTAs/SM (<=32 regs)
void bo4_fused_kernel(const float* __restrict__ yHat,
                      const float* __restrict__ prob,
                      const int*   __restrict__ y,
                      const int*   __restrict__ ind,
                      float*       __restrict__ out)
{
    const int b    = blockIdx.x;
    const int tid  = threadIdx.x;
    const int wid  = tid >> 5;
    const int lane = tid & 31;

    const float*  row  = yHat + (size_t)b * VOCAB;
    const float4* row4 = reinterpret_cast<const float4*>(row);

    // ---- PREFETCH tail operands (warp 0) so their DRAM/L2 latency ----
    // ---- overlaps the row scan instead of trailing it.             ----
    float pre_yg = 0.f, pre_c = 0.f, pre_p = 1.f;
    if (wid == 0) {
        const int yy = __ldg(y + b);            // uniform across warp
        pre_yg = __ldg(row + yy);
        if (lane < KNEG) {
            const int idx = __ldg(ind + b * KNEG + lane);   // idx in [0,100)
            pre_c = __ldg(row + idx);
            pre_p = __ldg(prob + (size_t)yy * SDOM + idx);
        }
    }

    // ---- row max over 32000 floats (8000 float4), streaming ----
    float m = -CUDART_INF_F;
    #pragma unroll 4
    for (int i = tid; i < VOCAB / 4; i += 256) {
        float4 v = __ldcs(row4 + i);            // evict-first: one-pass stream
        m = fmaxf(m, fmaxf(fmaxf(v.x, v.y), fmaxf(v.z, v.w)));
    }
    #pragma unroll
    for (int o = 16; o > 0; o >>= 1)
        m = fmaxf(m, __shfl_xor_sync(0xFFFFFFFFu, m, o));

    __shared__ float smax[8];
    if (lane == 0) smax[wid] = m;
    __syncthreads();

    // ---- warp-cooperative tail: pure ALU, operands already in regs ----
    if (wid == 0) {
        float mm = smax[0];
        #pragma unroll
        for (int w = 1; w < 8; w++) mm = fmaxf(mm, smax[w]);

        const float pinv = 1.0f / pre_p;                        // lanes>=K: 1.0
        float qv = (lane < KNEG) ? pinv : CUDART_INF_F;
        #pragma unroll
        for (int o = 16; o > 0; o >>= 1)
            qv = fminf(qv, __shfl_xor_sync(0xFFFFFFFFu, qv, o));

        const float ck = (lane < KNEG) ? pinv * __expf(pre_c - mm) : 0.f;
        float sc = ck;
        #pragma unroll
        for (int o = 16; o > 0; o >>= 1)
            sc += __shfl_xor_sync(0xFFFFFFFFu, sc, o);

        const float Yg  = qv * __expf(pre_yg - mm);   // pre_yg lane-uniform
        const float inv = 1.0f / (Yg + sc);

        float lt = (lane < KNEG) ? __logf(1.0f - ck * inv + EPSV) : 0.f;
        #pragma unroll
        for (int o = 16; o > 0; o >>= 1)
            lt += __shfl_xor_sync(0xFFFFFFFFu, lt, o);

        if (lane == 0) {
            const float term = __logf(Yg * inv + EPSV) + lt;
            atomicAdd(&g_acc, (double)term);
            __threadfence();
            unsigned int t = atomicAdd(&g_count, 1u);
            if (t == (unsigned)(B_ROWS - 1)) {
                out[0] = (float)(-g_acc / (double)(B_ROWS * (KNEG + 1)));
                g_acc   = 0.0;      // restore state for next graph replay
                g_count = 0u;
                __threadfence();
            }
        }
    }
}

extern "C" void kernel_launch(void* const* d_in, const int* in_sizes, int n_in,
                              void* d_out, int out_size)
{
    const float* yHat = (const float*)d_in[0];   // [B, V] fp32
    const float* prob = (const float*)d_in[1];   // [V, S] fp32
    const int*   y    = (const int*)  d_in[2];   // [B]    int32
    const int*   ind  = (const int*)  d_in[3];   // [B, K] int32

    bo4_fused_kernel<<<B_ROWS, 256>>>(yHat, prob, y, ind, (float*)d_out);
}